// round 4
// baseline (speedup 1.0000x reference)
#include <cuda_runtime.h>

// ============================================================================
// HistCausalEncoder: B=16, T=64, P=64, IN=256, ACT=64, OUT=256, H=4, concat=1536
//
// z_t = b + Wo*o_t + sum_h Wa_h*a_{t-4+h}   (phase 1, parallel over all t)
//         + sum_h Wz_h*z_{t-4+h}            (phase 2, sequential launches over t)
//
// All GEMMs run fp32 via packed fma.rn.f32x2 (FFMA2, 2 MACs/instr) with
// column-pair-packed accumulators. Weights are pre-transposed into k-major
// scratch (g_Wk for phase 1, g_Wz for phase 2) by a tiny prep kernel.
// Phase 2 accumulates in-place into d_out, so d_out is the recurrence state.
// ============================================================================

// --- weight scratch (device globals: allocation-free scratch) ---
__device__ float g_Wk[512 * 256];   // [k][n], k = [a_{t-4}(64) a_{t-3} a_{t-2} a_{t-1} | o(256)]
__device__ float g_Wz[1024 * 256];  // [k][n], k = [z_{t-4}(256) z_{t-3} z_{t-2} z_{t-1}]

// --- packed-f32x2 helpers ---
__device__ __forceinline__ unsigned long long bcast2(float x) {
    unsigned long long r;
    unsigned int xi = __float_as_uint(x);
    asm("mov.b64 %0, {%1, %2};" : "=l"(r) : "r"(xi), "r"(xi));
    return r;
}
__device__ __forceinline__ void fma2(unsigned long long &d,
                                     unsigned long long a,
                                     unsigned long long b) {
    asm("fma.rn.f32x2 %0, %1, %2, %0;" : "+l"(d) : "l"(a), "l"(b));
}
__device__ __forceinline__ float2 up2(unsigned long long v) {
    float2 f;
    asm("mov.b64 {%0, %1}, %2;" : "=f"(f.x), "=f"(f.y) : "l"(v));
    return f;
}

// ============================================================================
// prep: gather/transpose W (256 x 1536, row-major) into k-major g_Wk / g_Wz
// ============================================================================
__global__ void prep_kernel(const float* __restrict__ W) {
    int idx = blockIdx.x * 256 + threadIdx.x;
    if (idx < 512 * 256) {
        int k = idx >> 8, n = idx & 255;
        int col = (k < 256) ? ((k >> 6) * 320 + 256 + (k & 63))  // a-history slot h=k/64
                            : (1280 + (k - 256));                // o features
        g_Wk[idx] = W[n * 1536 + col];
    } else {
        int idx2 = idx - 512 * 256;
        if (idx2 < 1024 * 256) {
            int k = idx2 >> 8, n = idx2 & 255;
            int col = (k >> 8) * 320 + (k & 255);                // z-history slot h=k/256
            g_Wz[idx2] = W[n * 1536 + col];
        }
    }
}

// ============================================================================
// phase 1: out[b,t,p,:] = bias + [a_{t-4..t-1}, o_t] (512) @ g_Wk (512x256)
// grid (4 colTiles, B*T), 256 thr, CTA tile 64(p) x 64(n), micro 4x4, KC=16
// ============================================================================
__global__ void __launch_bounds__(256) phase1_kernel(
    const float* __restrict__ o, const float* __restrict__ act,
    const float* __restrict__ bias, float* __restrict__ out)
{
    __shared__ __align__(16) float As[2][16 * 68];  // [k][row], pad 68 for bank/align
    __shared__ __align__(16) float Bs[2][16 * 64];  // [k][col]

    const int tid = threadIdx.x;
    const int colbase = blockIdx.x * 64;
    const int bt = blockIdx.y;
    const int b = bt >> 6, t = bt & 63;
    const int rg = tid >> 4, cg = tid & 15;         // micro-tile coords

    unsigned long long acc[4][2];
    #pragma unroll
    for (int r = 0; r < 4; ++r) { acc[r][0] = 0ull; acc[r][1] = 0ull; }

    float ra[4], rb[4];
    const int akk = tid & 15, ar0 = tid >> 4;       // A-load mapping
    const int bcl = tid & 63, bkk = tid >> 6;       // B-load mapping

    auto loadChunk = [&](int cc) {
        const int kbase = cc * 16;
        const int k = kbase + akk;
        if (kbase < 256) {                           // a-history region
            const int h = k >> 6, j = k & 63;        // h uniform per chunk (16|64)
            const int ts = t - 4 + h;
            if (ts >= 0) {
                const float* base = act + (b * 64 + ts) * 4096 + j;   // P*ACT=4096
                #pragma unroll
                for (int q = 0; q < 4; ++q) ra[q] = base[(ar0 + q * 16) * 64];
            } else {
                #pragma unroll
                for (int q = 0; q < 4; ++q) ra[q] = 0.f;
            }
        } else {                                     // o region
            const int i = k - 256;
            const float* base = o + (b * 64 + t) * 16384 + i;          // P*IN=16384
            #pragma unroll
            for (int q = 0; q < 4; ++q) ra[q] = base[(ar0 + q * 16) * 256];
        }
        const float* wb = g_Wk + (kbase + bkk) * 256 + colbase + bcl;
        #pragma unroll
        for (int q = 0; q < 4; ++q) rb[q] = wb[q * 4 * 256];
    };

    auto stsChunk = [&](int buf) {
        #pragma unroll
        for (int q = 0; q < 4; ++q) As[buf][akk * 68 + ar0 + q * 16] = ra[q];
        #pragma unroll
        for (int q = 0; q < 4; ++q) Bs[buf][(bkk + q * 4) * 64 + bcl] = rb[q];
    };

    auto compute = [&](int buf) {
        #pragma unroll
        for (int kk = 0; kk < 16; ++kk) {
            const float4 a4 = *reinterpret_cast<const float4*>(&As[buf][kk * 68 + rg * 4]);
            const ulonglong2 bq = *reinterpret_cast<const ulonglong2*>(&Bs[buf][kk * 64 + cg * 4]);
            unsigned long long a0 = bcast2(a4.x), a1 = bcast2(a4.y);
            unsigned long long a2 = bcast2(a4.z), a3 = bcast2(a4.w);
            fma2(acc[0][0], a0, bq.x); fma2(acc[0][1], a0, bq.y);
            fma2(acc[1][0], a1, bq.x); fma2(acc[1][1], a1, bq.y);
            fma2(acc[2][0], a2, bq.x); fma2(acc[2][1], a2, bq.y);
            fma2(acc[3][0], a3, bq.x); fma2(acc[3][1], a3, bq.y);
        }
    };

    const int NC = 32;                               // K=512 / 16
    loadChunk(0); stsChunk(0);
    loadChunk(1);
    __syncthreads();
    for (int cc = 0; cc < NC; ++cc) {
        const int nb = (cc + 1) & 1;
        if (cc + 1 < NC) stsChunk(nb);               // ra/rb hold chunk cc+1
        if (cc + 2 < NC) loadChunk(cc + 2);          // prefetch next into regs
        compute(cc & 1);
        __syncthreads();
    }

    const int col = colbase + cg * 4;
    const float4 bv = *reinterpret_cast<const float4*>(&bias[col]);
    #pragma unroll
    for (int r = 0; r < 4; ++r) {
        float2 x0 = up2(acc[r][0]);
        float2 x1 = up2(acc[r][1]);
        float4 ov = make_float4(x0.x + bv.x, x0.y + bv.y, x1.x + bv.z, x1.y + bv.w);
        const int row = rg * 4 + r;                  // row == p
        *reinterpret_cast<float4*>(&out[((b * 64 + t) * 64 + row) * 256 + col]) = ov;
    }
}

// ============================================================================
// phase 2 (per t): out[:,t,:,:] += z[t-4..t-1] (K up to 1024) @ g_Wz (1024x256)
// grid (4 colTiles, 32 rowTiles) = 128 CTAs; 256 thr split in two K-halves,
// each half: CTA tile 32(row) x 64(n), micro 4x4, KC=32 per chunk (16/half).
// Smem reduction across halves, then read-modify-write into out.
// ============================================================================
__global__ void __launch_bounds__(256) phase2_kernel(float* __restrict__ out, const int t)
{
    __shared__ __align__(16) float As[2][32 * 36];  // [k][row], pad 36 (144B, 16B-aligned)
    __shared__ __align__(16) float Bs[2][32 * 64];  // [k][col]

    const int tid = threadIdx.x;
    const int colbase = blockIdx.x * 64;
    const int R0 = blockIdx.y * 32;                 // global row base (b,p flattened)
    const int b = R0 >> 6, p0 = R0 & 63;
    const int half = tid >> 7, tl = tid & 127;
    const int rg = tl >> 4, cg = tl & 15;

    const int h0 = (t >= 4) ? 0 : (4 - t);          // first valid history slot
    const int kStart = h0 << 8;
    const int NC = (1024 - kStart) >> 5;            // >= 8 for t >= 1

    unsigned long long acc[4][2];
    #pragma unroll
    for (int r = 0; r < 4; ++r) { acc[r][0] = 0ull; acc[r][1] = 0ull; }

    float ra[4], rb[8];
    const int akk = tid & 31, arr = tid >> 5;
    const int bcl = tid & 63, bkk = tid >> 6;

    auto loadChunk = [&](int cc) {
        const int kbase = kStart + cc * 32;
        const int h = kbase >> 8;                    // uniform per chunk (32|256)
        const int ts = t - 4 + h;                    // >= 0 by construction
        const int i0 = kbase & 255;
        const float* base = out + ((b * 64 + ts) * 64 + p0) * 256 + i0 + akk;
        #pragma unroll
        for (int q = 0; q < 4; ++q) ra[q] = base[(arr + q * 8) * 256];
        const float* wb = g_Wz + (kbase + bkk) * 256 + colbase + bcl;
        #pragma unroll
        for (int q = 0; q < 8; ++q) rb[q] = wb[q * 4 * 256];
    };

    auto stsChunk = [&](int buf) {
        #pragma unroll
        for (int q = 0; q < 4; ++q) As[buf][akk * 36 + arr + q * 8] = ra[q];
        #pragma unroll
        for (int q = 0; q < 8; ++q) Bs[buf][(bkk + q * 4) * 64 + bcl] = rb[q];
    };

    auto compute = [&](int buf) {
        const int k0 = half * 16;
        #pragma unroll
        for (int kk = 0; kk < 16; ++kk) {
            const int kx = k0 + kk;
            const float4 a4 = *reinterpret_cast<const float4*>(&As[buf][kx * 36 + rg * 4]);
            const ulonglong2 bq = *reinterpret_cast<const ulonglong2*>(&Bs[buf][kx * 64 + cg * 4]);
            unsigned long long a0 = bcast2(a4.x), a1 = bcast2(a4.y);
            unsigned long long a2 = bcast2(a4.z), a3 = bcast2(a4.w);
            fma2(acc[0][0], a0, bq.x); fma2(acc[0][1], a0, bq.y);
            fma2(acc[1][0], a1, bq.x); fma2(acc[1][1], a1, bq.y);
            fma2(acc[2][0], a2, bq.x); fma2(acc[2][1], a2, bq.y);
            fma2(acc[3][0], a3, bq.x); fma2(acc[3][1], a3, bq.y);
        }
    };

    loadChunk(0); stsChunk(0);
    loadChunk(1);
    __syncthreads();
    for (int cc = 0; cc < NC; ++cc) {
        const int nb = (cc + 1) & 1;
        if (cc + 1 < NC) stsChunk(nb);
        if (cc + 2 < NC) loadChunk(cc + 2);
        compute(cc & 1);
        __syncthreads();
    }

    // reduce the two K-halves through smem (reuse Bs[0]: 128 thr * 8 u64 = 8 KB)
    unsigned long long* red = reinterpret_cast<unsigned long long*>(&Bs[0][0]);
    if (half == 1) {
        #pragma unroll
        for (int r = 0; r < 4; ++r) {
            red[tl * 8 + r * 2]     = acc[r][0];
            red[tl * 8 + r * 2 + 1] = acc[r][1];
        }
    }
    __syncthreads();
    if (half == 0) {
        const int col = colbase + cg * 4;
        #pragma unroll
        for (int r = 0; r < 4; ++r) {
            float2 m0 = up2(acc[r][0]), m1 = up2(acc[r][1]);
            float2 o0 = up2(red[tl * 8 + r * 2]);
            float2 o1 = up2(red[tl * 8 + r * 2 + 1]);
            const int row = p0 + rg * 4 + r;
            float4* ptr = reinterpret_cast<float4*>(
                &out[((b * 64 + t) * 64 + row) * 256 + col]);
            float4 cur = *ptr;
            cur.x += m0.x + o0.x; cur.y += m0.y + o0.y;
            cur.z += m1.x + o1.x; cur.w += m1.y + o1.y;
            *ptr = cur;
        }
    }
}

// ============================================================================
// launch: prep -> phase1 -> 63 ordered phase2 launches (graph-capturable)
// ============================================================================
extern "C" void kernel_launch(void* const* d_in, const int* in_sizes, int n_in,
                              void* d_out, int out_size)
{
    const float* o_in  = (const float*)d_in[0];   // (16,64,64,256)
    const float* a_in  = (const float*)d_in[1];   // (16,64,64,64)
    const float* W_in  = (const float*)d_in[2];   // (256,1536)
    const float* b_in  = (const float*)d_in[3];   // (256,)
    float* out = (float*)d_out;                   // (16,64,64,256)

    prep_kernel<<<1536, 256>>>(W_in);
    phase1_kernel<<<dim3(4, 1024), 256>>>(o_in, a_in, b_in, out);
    for (int t = 1; t < 64; ++t)                  // t=0 has no recurrence terms
        phase2_kernel<<<dim3(4, 32), 256>>>(out, t);
}

// round 5
// speedup vs baseline: 1.0023x; 1.0023x over previous
#include <cuda_runtime.h>

// ============================================================================
// HistCausalEncoder: B=16, T=64, P=64, IN=256, ACT=64, OUT=256, H=4, concat=1536
//
// z_t = b + Wo*o_t + sum_h Wa_h*a_{t-4+h}   (phase 1, parallel over all t)
//         + sum_h Wz_h*z_{t-4+h}            (phase 2, sequential launches over t)
//
// All GEMMs run fp32 via packed fma.rn.f32x2 (FFMA2, 2 MACs/instr) with
// column-pair-packed accumulators. Weights are pre-transposed into k-major
// scratch (g_Wk for phase 1, g_Wz for phase 2) by a tiny prep kernel.
// Phase 2 accumulates in-place into d_out, so d_out is the recurrence state.
// ============================================================================

// --- weight scratch (device globals: allocation-free scratch) ---
__device__ float g_Wk[512 * 256];   // [k][n], k = [a_{t-4}(64) a_{t-3} a_{t-2} a_{t-1} | o(256)]
__device__ float g_Wz[1024 * 256];  // [k][n], k = [z_{t-4}(256) z_{t-3} z_{t-2} z_{t-1}]

// --- packed-f32x2 helpers ---
__device__ __forceinline__ unsigned long long bcast2(float x) {
    unsigned long long r;
    unsigned int xi = __float_as_uint(x);
    asm("mov.b64 %0, {%1, %2};" : "=l"(r) : "r"(xi), "r"(xi));
    return r;
}
__device__ __forceinline__ void fma2(unsigned long long &d,
                                     unsigned long long a,
                                     unsigned long long b) {
    asm("fma.rn.f32x2 %0, %1, %2, %0;" : "+l"(d) : "l"(a), "l"(b));
}
__device__ __forceinline__ float2 up2(unsigned long long v) {
    float2 f;
    asm("mov.b64 {%0, %1}, %2;" : "=f"(f.x), "=f"(f.y) : "l"(v));
    return f;
}

// ============================================================================
// prep: gather/transpose W (256 x 1536, row-major) into k-major g_Wk / g_Wz
// ============================================================================
__global__ void prep_kernel(const float* __restrict__ W) {
    int idx = blockIdx.x * 256 + threadIdx.x;
    if (idx < 512 * 256) {
        int k = idx >> 8, n = idx & 255;
        int col = (k < 256) ? ((k >> 6) * 320 + 256 + (k & 63))  // a-history slot h=k/64
                            : (1280 + (k - 256));                // o features
        g_Wk[idx] = W[n * 1536 + col];
    } else {
        int idx2 = idx - 512 * 256;
        if (idx2 < 1024 * 256) {
            int k = idx2 >> 8, n = idx2 & 255;
            int col = (k >> 8) * 320 + (k & 255);                // z-history slot h=k/256
            g_Wz[idx2] = W[n * 1536 + col];
        }
    }
}

// ============================================================================
// phase 1: out[b,t,p,:] = bias + [a_{t-4..t-1}, o_t] (512) @ g_Wk (512x256)
// grid (4 colTiles, B*T), 256 thr, CTA tile 64(p) x 64(n), micro 4x4, KC=16
// ============================================================================
__global__ void __launch_bounds__(256) phase1_kernel(
    const float* __restrict__ o, const float* __restrict__ act,
    const float* __restrict__ bias, float* __restrict__ out)
{
    __shared__ __align__(16) float As[2][16 * 68];  // [k][row], pad 68 for bank/align
    __shared__ __align__(16) float Bs[2][16 * 64];  // [k][col]

    const int tid = threadIdx.x;
    const int colbase = blockIdx.x * 64;
    const int bt = blockIdx.y;
    const int b = bt >> 6, t = bt & 63;
    const int rg = tid >> 4, cg = tid & 15;         // micro-tile coords

    unsigned long long acc[4][2];
    #pragma unroll
    for (int r = 0; r < 4; ++r) { acc[r][0] = 0ull; acc[r][1] = 0ull; }

    float ra[4], rb[4];
    const int akk = tid & 15, ar0 = tid >> 4;       // A-load mapping
    const int bcl = tid & 63, bkk = tid >> 6;       // B-load mapping

    auto loadChunk = [&](int cc) {
        const int kbase = cc * 16;
        const int k = kbase + akk;
        if (kbase < 256) {                           // a-history region
            const int h = k >> 6, j = k & 63;        // h uniform per chunk (16|64)
            const int ts = t - 4 + h;
            if (ts >= 0) {
                const float* base = act + (b * 64 + ts) * 4096 + j;   // P*ACT=4096
                #pragma unroll
                for (int q = 0; q < 4; ++q) ra[q] = base[(ar0 + q * 16) * 64];
            } else {
                #pragma unroll
                for (int q = 0; q < 4; ++q) ra[q] = 0.f;
            }
        } else {                                     // o region
            const int i = k - 256;
            const float* base = o + (b * 64 + t) * 16384 + i;          // P*IN=16384
            #pragma unroll
            for (int q = 0; q < 4; ++q) ra[q] = base[(ar0 + q * 16) * 256];
        }
        const float* wb = g_Wk + (kbase + bkk) * 256 + colbase + bcl;
        #pragma unroll
        for (int q = 0; q < 4; ++q) rb[q] = wb[q * 4 * 256];
    };

    auto stsChunk = [&](int buf) {
        #pragma unroll
        for (int q = 0; q < 4; ++q) As[buf][akk * 68 + ar0 + q * 16] = ra[q];
        #pragma unroll
        for (int q = 0; q < 4; ++q) Bs[buf][(bkk + q * 4) * 64 + bcl] = rb[q];
    };

    auto compute = [&](int buf) {
        #pragma unroll
        for (int kk = 0; kk < 16; ++kk) {
            const float4 a4 = *reinterpret_cast<const float4*>(&As[buf][kk * 68 + rg * 4]);
            const ulonglong2 bq = *reinterpret_cast<const ulonglong2*>(&Bs[buf][kk * 64 + cg * 4]);
            unsigned long long a0 = bcast2(a4.x), a1 = bcast2(a4.y);
            unsigned long long a2 = bcast2(a4.z), a3 = bcast2(a4.w);
            fma2(acc[0][0], a0, bq.x); fma2(acc[0][1], a0, bq.y);
            fma2(acc[1][0], a1, bq.x); fma2(acc[1][1], a1, bq.y);
            fma2(acc[2][0], a2, bq.x); fma2(acc[2][1], a2, bq.y);
            fma2(acc[3][0], a3, bq.x); fma2(acc[3][1], a3, bq.y);
        }
    };

    const int NC = 32;                               // K=512 / 16
    loadChunk(0); stsChunk(0);
    loadChunk(1);
    __syncthreads();
    for (int cc = 0; cc < NC; ++cc) {
        const int nb = (cc + 1) & 1;
        if (cc + 1 < NC) stsChunk(nb);               // ra/rb hold chunk cc+1
        if (cc + 2 < NC) loadChunk(cc + 2);          // prefetch next into regs
        compute(cc & 1);
        __syncthreads();
    }

    const int col = colbase + cg * 4;
    const float4 bv = *reinterpret_cast<const float4*>(&bias[col]);
    #pragma unroll
    for (int r = 0; r < 4; ++r) {
        float2 x0 = up2(acc[r][0]);
        float2 x1 = up2(acc[r][1]);
        float4 ov = make_float4(x0.x + bv.x, x0.y + bv.y, x1.x + bv.z, x1.y + bv.w);
        const int row = rg * 4 + r;                  // row == p
        *reinterpret_cast<float4*>(&out[((b * 64 + t) * 64 + row) * 256 + col]) = ov;
    }
}

// ============================================================================
// phase 2 (per t): out[:,t,:,:] += z[t-4..t-1] (K up to 1024) @ g_Wz (1024x256)
// grid (4 colTiles, 32 rowTiles) = 128 CTAs; 256 thr split in two K-halves,
// each half: CTA tile 32(row) x 64(n), micro 4x4, KC=32 per chunk (16/half).
// Smem reduction across halves, then read-modify-write into out.
// ============================================================================
__global__ void __launch_bounds__(256) phase2_kernel(float* __restrict__ out, const int t)
{
    __shared__ __align__(16) float As[2][32 * 36];  // [k][row], pad 36 (144B, 16B-aligned)
    __shared__ __align__(16) float Bs[2][32 * 64];  // [k][col]

    const int tid = threadIdx.x;
    const int colbase = blockIdx.x * 64;
    const int R0 = blockIdx.y * 32;                 // global row base (b,p flattened)
    const int b = R0 >> 6, p0 = R0 & 63;
    const int half = tid >> 7, tl = tid & 127;
    const int rg = tl >> 4, cg = tl & 15;

    const int h0 = (t >= 4) ? 0 : (4 - t);          // first valid history slot
    const int kStart = h0 << 8;
    const int NC = (1024 - kStart) >> 5;            // >= 8 for t >= 1

    unsigned long long acc[4][2];
    #pragma unroll
    for (int r = 0; r < 4; ++r) { acc[r][0] = 0ull; acc[r][1] = 0ull; }

    float ra[4], rb[8];
    const int akk = tid & 31, arr = tid >> 5;
    const int bcl = tid & 63, bkk = tid >> 6;

    auto loadChunk = [&](int cc) {
        const int kbase = kStart + cc * 32;
        const int h = kbase >> 8;                    // uniform per chunk (32|256)
        const int ts = t - 4 + h;                    // >= 0 by construction
        const int i0 = kbase & 255;
        const float* base = out + ((b * 64 + ts) * 64 + p0) * 256 + i0 + akk;
        #pragma unroll
        for (int q = 0; q < 4; ++q) ra[q] = base[(arr + q * 8) * 256];
        const float* wb = g_Wz + (kbase + bkk) * 256 + colbase + bcl;
        #pragma unroll
        for (int q = 0; q < 8; ++q) rb[q] = wb[q * 4 * 256];
    };

    auto stsChunk = [&](int buf) {
        #pragma unroll
        for (int q = 0; q < 4; ++q) As[buf][akk * 36 + arr + q * 8] = ra[q];
        #pragma unroll
        for (int q = 0; q < 8; ++q) Bs[buf][(bkk + q * 4) * 64 + bcl] = rb[q];
    };

    auto compute = [&](int buf) {
        const int k0 = half * 16;
        #pragma unroll
        for (int kk = 0; kk < 16; ++kk) {
            const int kx = k0 + kk;
            const float4 a4 = *reinterpret_cast<const float4*>(&As[buf][kx * 36 + rg * 4]);
            const ulonglong2 bq = *reinterpret_cast<const ulonglong2*>(&Bs[buf][kx * 64 + cg * 4]);
            unsigned long long a0 = bcast2(a4.x), a1 = bcast2(a4.y);
            unsigned long long a2 = bcast2(a4.z), a3 = bcast2(a4.w);
            fma2(acc[0][0], a0, bq.x); fma2(acc[0][1], a0, bq.y);
            fma2(acc[1][0], a1, bq.x); fma2(acc[1][1], a1, bq.y);
            fma2(acc[2][0], a2, bq.x); fma2(acc[2][1], a2, bq.y);
            fma2(acc[3][0], a3, bq.x); fma2(acc[3][1], a3, bq.y);
        }
    };

    loadChunk(0); stsChunk(0);
    loadChunk(1);
    __syncthreads();
    for (int cc = 0; cc < NC; ++cc) {
        const int nb = (cc + 1) & 1;
        if (cc + 1 < NC) stsChunk(nb);
        if (cc + 2 < NC) loadChunk(cc + 2);
        compute(cc & 1);
        __syncthreads();
    }

    // reduce the two K-halves through smem (reuse Bs[0]: 128 thr * 8 u64 = 8 KB)
    unsigned long long* red = reinterpret_cast<unsigned long long*>(&Bs[0][0]);
    if (half == 1) {
        #pragma unroll
        for (int r = 0; r < 4; ++r) {
            red[tl * 8 + r * 2]     = acc[r][0];
            red[tl * 8 + r * 2 + 1] = acc[r][1];
        }
    }
    __syncthreads();
    if (half == 0) {
        const int col = colbase + cg * 4;
        #pragma unroll
        for (int r = 0; r < 4; ++r) {
            float2 m0 = up2(acc[r][0]), m1 = up2(acc[r][1]);
            float2 o0 = up2(red[tl * 8 + r * 2]);
            float2 o1 = up2(red[tl * 8 + r * 2 + 1]);
            const int row = p0 + rg * 4 + r;
            float4* ptr = reinterpret_cast<float4*>(
                &out[((b * 64 + t) * 64 + row) * 256 + col]);
            float4 cur = *ptr;
            cur.x += m0.x + o0.x; cur.y += m0.y + o0.y;
            cur.z += m1.x + o1.x; cur.w += m1.y + o1.y;
            *ptr = cur;
        }
    }
}

// ============================================================================
// launch: prep -> phase1 -> 63 ordered phase2 launches (graph-capturable)
// ============================================================================
extern "C" void kernel_launch(void* const* d_in, const int* in_sizes, int n_in,
                              void* d_out, int out_size)
{
    const float* o_in  = (const float*)d_in[0];   // (16,64,64,256)
    const float* a_in  = (const float*)d_in[1];   // (16,64,64,64)
    const float* W_in  = (const float*)d_in[2];   // (256,1536)
    const float* b_in  = (const float*)d_in[3];   // (256,)
    float* out = (float*)d_out;                   // (16,64,64,256)

    prep_kernel<<<1536, 256>>>(W_in);
    phase1_kernel<<<dim3(4, 1024), 256>>>(o_in, a_in, b_in, out);
    for (int t = 1; t < 64; ++t)                  // t=0 has no recurrence terms
        phase2_kernel<<<dim3(4, 32), 256>>>(out, t);
}